// round 1
// baseline (speedup 1.0000x reference)
#include <cuda_runtime.h>
#include <math.h>

#define BQ  128   // batch
#define KK_ 49    // spatial locations / attn hidden
#define DD  512   // hidden dim
#define EE  256   // embedding dim
#define VV  10000 // vocab
#define TT  20    // max timesteps
#define G4  2048  // 4*D

// -------------------- device scratch (static, no allocation) --------------------
__device__ __align__(128) float g_embseq[BQ * TT * EE];   // gathered caption embeddings
__device__ __align__(128) float g_hbuf[2][BQ * DD];       // double-buffered h
__device__ __align__(128) float g_mstate[BQ * DD];        // LSTM cell state
__device__ __align__(128) float g_gxg[BQ * G4];           // global part of input gates (+b_ih)
__device__ __align__(128) float g_gatesx[BQ * TT * G4];   // full precomputed x@W_ih^T + b_ih
__device__ __align__(128) float g_vproj[BQ * KK_ * KK_];  // spatial @ Wv^T + bv
__device__ __align__(128) float g_part[BQ * 8 * G4];      // split-K partials of h@W_hh^T
__device__ __align__(128) float g_s[BQ * TT * DD];        // s_t = c_t + h_t
__device__ unsigned g_barcnt = 0;
__device__ unsigned g_bargen = 0;

// -------------------- embedding gather --------------------
__global__ void gather_emb(const int* __restrict__ cap,
                           const float* __restrict__ emb,
                           float* __restrict__ out) {
    int i = blockIdx.x * blockDim.x + threadIdx.x;   // float4 index
    int total = BQ * TT * (EE / 4);
    if (i < total) {
        int m  = i / (EE / 4);
        int e4 = i - m * (EE / 4);
        int tok = cap[m];
        reinterpret_cast<float4*>(out)[(size_t)m * (EE / 4) + e4] =
            reinterpret_cast<const float4*>(emb)[(size_t)tok * (EE / 4) + e4];
    }
}

// -------------------- generic SGEMM: C[M,N] = A[M,K] @ B[N,K]^T (+epilogue) ----
// 128x128 tile, BK=8, 256 threads, 8x8 micro-tile (4/64-split to reduce bank conflicts)
__global__ __launch_bounds__(256) void gemm_nt(
    const float* __restrict__ A, int lda,
    const float* __restrict__ B, int ldb,
    float* __restrict__ C, int ldc,
    int M, int N, int Kd,
    const float* __restrict__ bias,                 // [N] or null
    const float* __restrict__ rowAdd, int rowDiv, int ldra, // C += rowAdd[(m/rowDiv)*ldra + n]
    const int* __restrict__ mlen, int maskT)        // zero row m if mlen[m/maskT] <= m%maskT
{
    __shared__ float As[8][128];
    __shared__ float Bs[8][128];
    const int bm = blockIdx.y * 128;
    const int bn = blockIdx.x * 128;
    const int tid = threadIdx.x;
    const int tx = tid & 15;
    const int ty = tid >> 4;
    const int lr = tid >> 1;
    const int lk = (tid & 1) * 4;

    float acc[8][8];
#pragma unroll
    for (int i = 0; i < 8; i++)
#pragma unroll
        for (int j = 0; j < 8; j++) acc[i][j] = 0.f;

    for (int k0 = 0; k0 < Kd; k0 += 8) {
        float4 va = make_float4(0.f, 0.f, 0.f, 0.f);
        float4 vb = make_float4(0.f, 0.f, 0.f, 0.f);
        int gm = bm + lr;
        int gn = bn + lr;
        if (gm < M) va = *reinterpret_cast<const float4*>(A + (size_t)gm * lda + k0 + lk);
        if (gn < N) vb = *reinterpret_cast<const float4*>(B + (size_t)gn * ldb + k0 + lk);
        As[lk + 0][lr] = va.x; As[lk + 1][lr] = va.y; As[lk + 2][lr] = va.z; As[lk + 3][lr] = va.w;
        Bs[lk + 0][lr] = vb.x; Bs[lk + 1][lr] = vb.y; Bs[lk + 2][lr] = vb.z; Bs[lk + 3][lr] = vb.w;
        __syncthreads();
#pragma unroll
        for (int kk = 0; kk < 8; kk++) {
            float a[8], bb[8];
            *(float4*)&a[0]  = *(const float4*)&As[kk][ty * 4];
            *(float4*)&a[4]  = *(const float4*)&As[kk][64 + ty * 4];
            *(float4*)&bb[0] = *(const float4*)&Bs[kk][tx * 4];
            *(float4*)&bb[4] = *(const float4*)&Bs[kk][64 + tx * 4];
#pragma unroll
            for (int i = 0; i < 8; i++)
#pragma unroll
                for (int j = 0; j < 8; j++)
                    acc[i][j] = fmaf(a[i], bb[j], acc[i][j]);
        }
        __syncthreads();
    }

#pragma unroll
    for (int i = 0; i < 8; i++) {
        int gm = bm + ((i < 4) ? (ty * 4 + i) : (64 + ty * 4 + i - 4));
        if (gm >= M) continue;
        bool zero = false;
        if (mlen) zero = (mlen[gm / maskT] <= (gm % maskT));
        const float* ra = rowAdd ? (rowAdd + (size_t)(gm / rowDiv) * ldra) : nullptr;
#pragma unroll
        for (int j = 0; j < 8; j++) {
            int gn = bn + ((j < 4) ? (tx * 4 + j) : (64 + tx * 4 + j - 4));
            if (gn >= N) continue;
            float v = acc[i][j];
            if (bias) v += bias[gn];
            if (ra)   v += ra[gn];
            if (zero) v = 0.f;
            C[(size_t)gm * ldc + gn] = v;
        }
    }
}

// -------------------- grid barrier (128 co-resident CTAs) --------------------
__device__ __forceinline__ void gridbar() {
    __syncthreads();
    if (threadIdx.x == 0) {
        unsigned g = *(volatile unsigned*)&g_bargen;
        __threadfence();
        if (atomicAdd(&g_barcnt, 1u) == gridDim.x - 1) {
            g_barcnt = 0;
            __threadfence();
            atomicExch(&g_bargen, g + 1u);
        } else {
            while (*(volatile unsigned*)&g_bargen == g) { __nanosleep(40); }
        }
        __threadfence();
    }
    __syncthreads();
}

// -------------------- persistent recurrence kernel --------------------
// grid = 128 CTAs x 256 threads; per step:
//   phase1: split-K gates GEMM  part[b][kc][j] = h @ W_hh^T chunk  (kc = blk&7, cg = blk>>3)
//   barrier
//   phase2: CTA b: reduce partials + gates_x -> LSTM -> attention -> s[b,t,:]
//   barrier
__global__ __launch_bounds__(256, 1) void recur_kernel(
    const float* __restrict__ W_hh,    // [2048,512]
    const float* __restrict__ b_hh,    // [2048]
    const int*   __restrict__ lengths, // [128]
    const float* __restrict__ spatial, // [128,49,512]
    const float* __restrict__ Wg,      // [49,512]
    const float* __restrict__ bg,      // [49]
    const float* __restrict__ wh,      // [49]
    const float* __restrict__ bh_att)  // [1]
{
    __shared__ float As[8][128];
    __shared__ float Bs[8][128];
    __shared__ float sh_h[DD];
    __shared__ float sh_gh[52];
    __shared__ float sh_z[52];
    __shared__ float sh_alpha[52];

    const int c = blockIdx.x;
    const int tid = threadIdx.x;
    const int tx = tid & 15, ty = tid >> 4;
    const int lr = tid >> 1, lk = (tid & 1) * 4;
    const int kc = c & 7, cg = c >> 3;
    const int b = c;
    const int wid = tid >> 5, lane = tid & 31;
    const float bh0 = bh_att[0];
    int cur = 0;

    for (int t = 0; t < TT; t++) {
        // ---------------- phase 1: gates split-K GEMM ----------------
        {
            const float* hc = g_hbuf[cur];
            float acc[8][8];
#pragma unroll
            for (int i = 0; i < 8; i++)
#pragma unroll
                for (int j = 0; j < 8; j++) acc[i][j] = 0.f;
            const int kbase = kc * 64;
            for (int k0 = 0; k0 < 64; k0 += 8) {
                float4 va = *(const float4*)(hc + (size_t)lr * DD + kbase + k0 + lk);
                float4 vb = *(const float4*)(W_hh + (size_t)(cg * 128 + lr) * DD + kbase + k0 + lk);
                As[lk + 0][lr] = va.x; As[lk + 1][lr] = va.y; As[lk + 2][lr] = va.z; As[lk + 3][lr] = va.w;
                Bs[lk + 0][lr] = vb.x; Bs[lk + 1][lr] = vb.y; Bs[lk + 2][lr] = vb.z; Bs[lk + 3][lr] = vb.w;
                __syncthreads();
#pragma unroll
                for (int kk = 0; kk < 8; kk++) {
                    float a[8], bb[8];
                    *(float4*)&a[0]  = *(const float4*)&As[kk][ty * 4];
                    *(float4*)&a[4]  = *(const float4*)&As[kk][64 + ty * 4];
                    *(float4*)&bb[0] = *(const float4*)&Bs[kk][tx * 4];
                    *(float4*)&bb[4] = *(const float4*)&Bs[kk][64 + tx * 4];
#pragma unroll
                    for (int i = 0; i < 8; i++)
#pragma unroll
                        for (int j = 0; j < 8; j++)
                            acc[i][j] = fmaf(a[i], bb[j], acc[i][j]);
                }
                __syncthreads();
            }
#pragma unroll
            for (int i = 0; i < 8; i++) {
                int r = (i < 4) ? (ty * 4 + i) : (64 + ty * 4 + i - 4);
                float* pr = g_part + (size_t)r * (8 * G4) + kc * G4 + cg * 128;
#pragma unroll
                for (int j = 0; j < 8; j++) {
                    int cix = (j < 4) ? (tx * 4 + j) : (64 + tx * 4 + j - 4);
                    pr[cix] = acc[i][j];
                }
            }
        }
        gridbar();
        // ---------------- phase 2: per-batch LSTM + attention ----------------
        {
            const bool active = lengths[b] > t;
            const float* hc = g_hbuf[cur] + (size_t)b * DD;
            float* hn = g_hbuf[cur ^ 1] + (size_t)b * DD;
            float* mm = g_mstate + (size_t)b * DD;
            const float* gx = g_gatesx + (size_t)(b * TT + t) * G4;
            const float* pp = g_part + (size_t)b * (8 * G4);
            for (int d = tid; d < DD; d += 256) {
                float gi = gx[d]        + b_hh[d];
                float gf = gx[512 + d]  + b_hh[512 + d];
                float gg = gx[1024 + d] + b_hh[1024 + d];
                float go = gx[1536 + d] + b_hh[1536 + d];
#pragma unroll
                for (int q = 0; q < 8; q++) {
                    const float* p = pp + q * G4;
                    gi += p[d]; gf += p[512 + d]; gg += p[1024 + d]; go += p[1536 + d];
                }
                float ig = 1.f / (1.f + expf(-gi));
                float fg = 1.f / (1.f + expf(-gf));
                float og = 1.f / (1.f + expf(-go));
                float gt = tanhf(gg);
                float mo = mm[d];
                float mn = fg * mo + ig * gt;
                float hv = og * tanhf(mn);
                if (!active) { mn = mo; hv = hc[d]; }
                mm[d] = mn;
                hn[d] = hv;
                sh_h[d] = hv;
            }
            __syncthreads();
            if (active) {  // uniform branch per CTA
                // gh[k] = Wg[k,:] . h + bg[k]
                for (int k = wid; k < KK_; k += 8) {
                    const float* wr = Wg + (size_t)k * DD;
                    float s = 0.f;
                    for (int q = lane; q < DD; q += 32) s = fmaf(wr[q], sh_h[q], s);
#pragma unroll
                    for (int o = 16; o; o >>= 1) s += __shfl_xor_sync(0xffffffffu, s, o);
                    if (lane == 0) sh_gh[k] = s + bg[k];
                }
                __syncthreads();
                // z[k] = sum_q tanh(vproj[b,k,q] + gh[q]) * wh[q] + bh
                for (int k = wid; k < KK_; k += 8) {
                    const float* vp = g_vproj + (size_t)(b * KK_ + k) * KK_;
                    float s = 0.f;
                    for (int q = lane; q < KK_; q += 32) s += tanhf(vp[q] + sh_gh[q]) * wh[q];
#pragma unroll
                    for (int o = 16; o; o >>= 1) s += __shfl_xor_sync(0xffffffffu, s, o);
                    if (lane == 0) sh_z[k] = s + bh0;
                }
                __syncthreads();
                if (wid == 0) {
                    float mx = -3.0e38f;
                    for (int k = lane; k < KK_; k += 32) mx = fmaxf(mx, sh_z[k]);
#pragma unroll
                    for (int o = 16; o; o >>= 1) mx = fmaxf(mx, __shfl_xor_sync(0xffffffffu, mx, o));
                    float sm = 0.f;
                    for (int k = lane; k < KK_; k += 32) { float e = expf(sh_z[k] - mx); sh_alpha[k] = e; sm += e; }
#pragma unroll
                    for (int o = 16; o; o >>= 1) sm += __shfl_xor_sync(0xffffffffu, sm, o);
                    float inv = 1.f / sm;
                    for (int k = lane; k < KK_; k += 32) sh_alpha[k] *= inv;
                }
                __syncthreads();
                float* so = g_s + (size_t)(b * TT + t) * DD;
                const float* sp = spatial + (size_t)b * KK_ * DD;
                for (int d = tid; d < DD; d += 256) {
                    float cc = 0.f;
#pragma unroll
                    for (int k = 0; k < KK_; k++) cc = fmaf(sh_alpha[k], sp[(size_t)k * DD + d], cc);
                    so[d] = cc + sh_h[d];
                }
            }
        }
        gridbar();
        cur ^= 1;
    }
}

// -------------------- launch --------------------
extern "C" void kernel_launch(void* const* d_in, const int* in_sizes, int n_in,
                              void* d_out, int out_size)
{
    const float* spatial      = (const float*)d_in[0];
    const float* global_feats = (const float*)d_in[1];
    const int*   captions     = (const int*)d_in[2];
    const int*   lengths      = (const int*)d_in[3];
    const float* emb          = (const float*)d_in[4];
    const float* W_init_h     = (const float*)d_in[5];
    const float* b_init_h     = (const float*)d_in[6];
    const float* W_init_m     = (const float*)d_in[7];
    const float* b_init_m     = (const float*)d_in[8];
    const float* W_ih         = (const float*)d_in[9];
    const float* b_ih         = (const float*)d_in[10];
    const float* W_hh         = (const float*)d_in[11];
    const float* b_hh         = (const float*)d_in[12];
    const float* Wv           = (const float*)d_in[13];
    const float* bv           = (const float*)d_in[14];
    const float* Wg           = (const float*)d_in[15];
    const float* bg           = (const float*)d_in[16];
    const float* wh           = (const float*)d_in[17];
    const float* bh_att       = (const float*)d_in[18];
    const float* Wp           = (const float*)d_in[19];
    const float* bp           = (const float*)d_in[20];
    float* out = (float*)d_out;

    float *p_embseq, *p_hbuf, *p_m, *p_gxg, *p_gatesx, *p_vproj, *p_s;
    cudaGetSymbolAddress((void**)&p_embseq, g_embseq);
    cudaGetSymbolAddress((void**)&p_hbuf,   g_hbuf);
    cudaGetSymbolAddress((void**)&p_m,      g_mstate);
    cudaGetSymbolAddress((void**)&p_gxg,    g_gxg);
    cudaGetSymbolAddress((void**)&p_gatesx, g_gatesx);
    cudaGetSymbolAddress((void**)&p_vproj,  g_vproj);
    cudaGetSymbolAddress((void**)&p_s,      g_s);

    // 1. gather caption embeddings -> [B*T, E]
    gather_emb<<<(BQ * TT * (EE / 4) + 255) / 256, 256>>>(captions, emb, p_embseq);

    // 2. h0 = global @ W_init_h^T + b_init_h   -> g_hbuf[0]
    gemm_nt<<<dim3(4, 1), 256>>>(global_feats, DD, W_init_h, DD, p_hbuf, DD,
                                 BQ, DD, DD, b_init_h, nullptr, 1, 0, nullptr, 1);
    // 3. m0 = global @ W_init_m^T + b_init_m   -> g_mstate
    gemm_nt<<<dim3(4, 1), 256>>>(global_feats, DD, W_init_m, DD, p_m, DD,
                                 BQ, DD, DD, b_init_m, nullptr, 1, 0, nullptr, 1);
    // 4. gxg = global @ W_ih[:,E:]^T + b_ih    -> [B, 4D]
    gemm_nt<<<dim3(16, 1), 256>>>(global_feats, DD, W_ih + EE, EE + DD, p_gxg, G4,
                                  BQ, G4, DD, b_ih, nullptr, 1, 0, nullptr, 1);
    // 5. gates_x = embseq @ W_ih[:,:E]^T + gxg[b]  -> [B*T, 4D]
    gemm_nt<<<dim3(16, 20), 256>>>(p_embseq, EE, W_ih, EE + DD, p_gatesx, G4,
                                   BQ * TT, G4, EE, nullptr, p_gxg, TT, G4, nullptr, 1);
    // 6. vproj = spatial @ Wv^T + bv           -> [B*K, K]
    gemm_nt<<<dim3(1, 49), 256>>>(spatial, DD, Wv, DD, p_vproj, KK_,
                                  BQ * KK_, KK_, DD, bv, nullptr, 1, 0, nullptr, 1);
    // 7. sequential recurrence (persistent, 128 co-resident CTAs)
    recur_kernel<<<128, 256>>>(W_hh, b_hh, lengths, spatial, Wg, bg, wh, bh_att);
    // 8. logits = s @ Wp^T + bp, zeroed where inactive  -> d_out [B*T, V]
    gemm_nt<<<dim3(79, 20), 256>>>(p_s, DD, Wp, DD, out, VV,
                                   BQ * TT, VV, DD, bp, nullptr, 1, 0, lengths, TT);
}

// round 2
// speedup vs baseline: 1.2490x; 1.2490x over previous
#include <cuda_runtime.h>
#include <cuda_bf16.h>
#include <math.h>
#include <stdint.h>

#define BQ  128   // batch
#define KK_ 49    // spatial locations / attn hidden
#define DD  512   // hidden dim
#define EE  256   // embedding dim
#define VV  10000 // vocab
#define TT  20    // max timesteps
#define G4  2048  // 4*D

// -------------------- device scratch (static, no allocation) --------------------
__device__ __align__(128) float g_embseq[BQ * TT * EE];   // gathered caption embeddings
__device__ __align__(128) float g_hbuf[2][BQ * DD];       // double-buffered h
__device__ __align__(128) float g_mstate[BQ * DD];        // LSTM cell state
__device__ __align__(128) float g_gxg[BQ * G4];           // global part of input gates (+b_ih)
__device__ __align__(128) float g_gatesx[BQ * TT * G4];   // full precomputed x@W_ih^T + b_ih
__device__ __align__(128) float g_vproj[BQ * KK_ * KK_];  // spatial @ Wv^T + bv
__device__ __align__(128) float g_part[BQ * 8 * G4];      // split-K partials of h@W_hh^T
__device__ __align__(128) float g_s[BQ * TT * DD];        // s_t = c_t + h_t
__device__ unsigned g_barcnt = 0;
__device__ unsigned g_bargen = 0;

// -------------------- embedding gather --------------------
__global__ void gather_emb(const int* __restrict__ cap,
                           const float* __restrict__ emb,
                           float* __restrict__ out) {
    int i = blockIdx.x * blockDim.x + threadIdx.x;   // float4 index
    int total = BQ * TT * (EE / 4);
    if (i < total) {
        int m  = i / (EE / 4);
        int e4 = i - m * (EE / 4);
        int tok = cap[m];
        reinterpret_cast<float4*>(out)[(size_t)m * (EE / 4) + e4] =
            reinterpret_cast<const float4*>(emb)[(size_t)tok * (EE / 4) + e4];
    }
}

// -------------------- bf16x3 tensor-core GEMM --------------------
// C[M,N] = A[M,K] @ B[N,K]^T (+bias +rowAdd, optional row zero-mask).
// fp32 inputs are split in-kernel into bf16 hi/lo; C = AhBh + AhBl + AlBh (fp32 acc).
// Tile 128x128, BK=32, 256 threads = 8 warps (2x4), warp tile 64x32,
// mma.sync.aligned.m16n8k16.row.col.f32.bf16.bf16.f32.

__device__ __forceinline__ void mma16816(float c[4], const uint32_t a[4], const uint32_t b[2]) {
    asm volatile(
        "mma.sync.aligned.m16n8k16.row.col.f32.bf16.bf16.f32 "
        "{%0,%1,%2,%3},{%4,%5,%6,%7},{%8,%9},{%0,%1,%2,%3};"
        : "+f"(c[0]), "+f"(c[1]), "+f"(c[2]), "+f"(c[3])
        : "r"(a[0]), "r"(a[1]), "r"(a[2]), "r"(a[3]), "r"(b[0]), "r"(b[1]));
}

#define SPAD 40  // smem row stride (bf16 elems): 20 words -> conflict-free 8x4 access

__global__ __launch_bounds__(256) void gemm_bf3(
    const float* __restrict__ A, int lda,
    const float* __restrict__ B, int ldb,
    float* __restrict__ C, int ldc,
    int M, int N, int Kd,
    const float* __restrict__ bias,                       // [N] or null
    const float* __restrict__ rowAdd, int rowDiv, int ldra, // C += rowAdd[(m/rowDiv)*ldra+n]
    const int* __restrict__ mlen, int maskT)              // zero row m if mlen[m/maskT] <= m%maskT
{
    __shared__ __nv_bfloat16 Ah[128][SPAD], Al[128][SPAD];
    __shared__ __nv_bfloat16 Bh[128][SPAD], Bl[128][SPAD];

    const int tid = threadIdx.x;
    const int bm = blockIdx.y * 128;
    const int bn = blockIdx.x * 128;
    const int w = tid >> 5, lane = tid & 31;
    const int wm = w >> 2, wn = w & 3;
    const int g = lane >> 2, tg = lane & 3;
    const int row0 = tid >> 3;          // 0..31
    const int c4 = (tid & 7) * 4;       // 0,4,..28

    float acc[4][4][4];
#pragma unroll
    for (int i = 0; i < 4; i++)
#pragma unroll
        for (int j = 0; j < 4; j++)
#pragma unroll
            for (int q = 0; q < 4; q++) acc[i][j][q] = 0.f;

    for (int k0 = 0; k0 < Kd; k0 += 32) {
        // ---- load fp32 tiles, split to bf16 hi/lo in smem ----
#pragma unroll
        for (int it = 0; it < 4; it++) {
            int r = row0 + it * 32;
            // A tile row
            {
                int gm = bm + r;
                float4 v = make_float4(0.f, 0.f, 0.f, 0.f);
                if (gm < M) v = *reinterpret_cast<const float4*>(A + (size_t)gm * lda + k0 + c4);
                float vv[4] = {v.x, v.y, v.z, v.w};
#pragma unroll
                for (int q = 0; q < 4; q++) {
                    __nv_bfloat16 hi = __float2bfloat16(vv[q]);
                    Ah[r][c4 + q] = hi;
                    Al[r][c4 + q] = __float2bfloat16(vv[q] - __bfloat162float(hi));
                }
            }
            // B tile row
            {
                int gn = bn + r;
                float4 v = make_float4(0.f, 0.f, 0.f, 0.f);
                if (gn < N) v = *reinterpret_cast<const float4*>(B + (size_t)gn * ldb + k0 + c4);
                float vv[4] = {v.x, v.y, v.z, v.w};
#pragma unroll
                for (int q = 0; q < 4; q++) {
                    __nv_bfloat16 hi = __float2bfloat16(vv[q]);
                    Bh[r][c4 + q] = hi;
                    Bl[r][c4 + q] = __float2bfloat16(vv[q] - __bfloat162float(hi));
                }
            }
        }
        __syncthreads();

        // ---- tensor-core compute: 2 k16 steps, 3 products each ----
#pragma unroll
        for (int ks = 0; ks < 32; ks += 16) {
            uint32_t bhf[4][2], blf[4][2];
#pragma unroll
            for (int ni = 0; ni < 4; ni++) {
                int n = wn * 32 + ni * 8 + g;
                bhf[ni][0] = *reinterpret_cast<const uint32_t*>(&Bh[n][ks + tg * 2]);
                bhf[ni][1] = *reinterpret_cast<const uint32_t*>(&Bh[n][ks + 8 + tg * 2]);
                blf[ni][0] = *reinterpret_cast<const uint32_t*>(&Bl[n][ks + tg * 2]);
                blf[ni][1] = *reinterpret_cast<const uint32_t*>(&Bl[n][ks + 8 + tg * 2]);
            }
#pragma unroll
            for (int mi = 0; mi < 4; mi++) {
                int m = wm * 64 + mi * 16;
                uint32_t ah[4], al[4];
                ah[0] = *reinterpret_cast<const uint32_t*>(&Ah[m + g][ks + tg * 2]);
                ah[1] = *reinterpret_cast<const uint32_t*>(&Ah[m + g + 8][ks + tg * 2]);
                ah[2] = *reinterpret_cast<const uint32_t*>(&Ah[m + g][ks + tg * 2 + 8]);
                ah[3] = *reinterpret_cast<const uint32_t*>(&Ah[m + g + 8][ks + tg * 2 + 8]);
                al[0] = *reinterpret_cast<const uint32_t*>(&Al[m + g][ks + tg * 2]);
                al[1] = *reinterpret_cast<const uint32_t*>(&Al[m + g + 8][ks + tg * 2]);
                al[2] = *reinterpret_cast<const uint32_t*>(&Al[m + g][ks + tg * 2 + 8]);
                al[3] = *reinterpret_cast<const uint32_t*>(&Al[m + g + 8][ks + tg * 2 + 8]);
#pragma unroll
                for (int ni = 0; ni < 4; ni++) {
                    mma16816(acc[mi][ni], ah, bhf[ni]);
                    mma16816(acc[mi][ni], ah, blf[ni]);
                    mma16816(acc[mi][ni], al, bhf[ni]);
                }
            }
        }
        __syncthreads();
    }

    // ---- epilogue ----
#pragma unroll
    for (int mi = 0; mi < 4; mi++) {
#pragma unroll
        for (int ni = 0; ni < 4; ni++) {
            int gn0 = bn + wn * 32 + ni * 8 + tg * 2;
            float* cr = acc[mi][ni];
#pragma unroll
            for (int half = 0; half < 2; half++) {
                int gm = bm + wm * 64 + mi * 16 + g + half * 8;
                if (gm >= M) continue;
                bool zero = mlen ? (mlen[gm / maskT] <= (gm % maskT)) : false;
                const float* ra = rowAdd ? (rowAdd + (size_t)(gm / rowDiv) * ldra) : nullptr;
                float v0 = cr[half * 2 + 0];
                float v1 = cr[half * 2 + 1];
                if (gn0 < N) {
                    float v = v0;
                    if (bias) v += bias[gn0];
                    if (ra)   v += ra[gn0];
                    if (zero) v = 0.f;
                    C[(size_t)gm * ldc + gn0] = v;
                }
                if (gn0 + 1 < N) {
                    float v = v1;
                    if (bias) v += bias[gn0 + 1];
                    if (ra)   v += ra[gn0 + 1];
                    if (zero) v = 0.f;
                    C[(size_t)gm * ldc + gn0 + 1] = v;
                }
            }
        }
    }
}

// -------------------- grid barrier (128 co-resident CTAs) --------------------
__device__ __forceinline__ void gridbar() {
    __syncthreads();
    if (threadIdx.x == 0) {
        unsigned g = *(volatile unsigned*)&g_bargen;
        __threadfence();
        if (atomicAdd(&g_barcnt, 1u) == gridDim.x - 1) {
            g_barcnt = 0;
            __threadfence();
            atomicExch(&g_bargen, g + 1u);
        } else {
            while (*(volatile unsigned*)&g_bargen == g) { __nanosleep(40); }
        }
        __threadfence();
    }
    __syncthreads();
}

// -------------------- persistent recurrence kernel --------------------
__global__ __launch_bounds__(256, 1) void recur_kernel(
    const float* __restrict__ W_hh,    // [2048,512]
    const float* __restrict__ b_hh,    // [2048]
    const int*   __restrict__ lengths, // [128]
    const float* __restrict__ spatial, // [128,49,512]
    const float* __restrict__ Wg,      // [49,512]
    const float* __restrict__ bg,      // [49]
    const float* __restrict__ wh,      // [49]
    const float* __restrict__ bh_att)  // [1]
{
    __shared__ float As[8][128];
    __shared__ float Bs[8][128];
    __shared__ float sh_h[DD];
    __shared__ float sh_gh[52];
    __shared__ float sh_z[52];
    __shared__ float sh_alpha[52];

    const int c = blockIdx.x;
    const int tid = threadIdx.x;
    const int tx = tid & 15, ty = tid >> 4;
    const int lr = tid >> 1, lk = (tid & 1) * 4;
    const int kc = c & 7, cg = c >> 3;
    const int b = c;
    const int wid = tid >> 5, lane = tid & 31;
    const float bh0 = bh_att[0];
    int cur = 0;

    for (int t = 0; t < TT; t++) {
        // ---------------- phase 1: gates split-K GEMM ----------------
        {
            const float* hc = g_hbuf[cur];
            float acc[8][8];
#pragma unroll
            for (int i = 0; i < 8; i++)
#pragma unroll
                for (int j = 0; j < 8; j++) acc[i][j] = 0.f;
            const int kbase = kc * 64;
            for (int k0 = 0; k0 < 64; k0 += 8) {
                float4 va = *(const float4*)(hc + (size_t)lr * DD + kbase + k0 + lk);
                float4 vb = *(const float4*)(W_hh + (size_t)(cg * 128 + lr) * DD + kbase + k0 + lk);
                As[lk + 0][lr] = va.x; As[lk + 1][lr] = va.y; As[lk + 2][lr] = va.z; As[lk + 3][lr] = va.w;
                Bs[lk + 0][lr] = vb.x; Bs[lk + 1][lr] = vb.y; Bs[lk + 2][lr] = vb.z; Bs[lk + 3][lr] = vb.w;
                __syncthreads();
#pragma unroll
                for (int kk = 0; kk < 8; kk++) {
                    float a[8], bb[8];
                    *(float4*)&a[0]  = *(const float4*)&As[kk][ty * 4];
                    *(float4*)&a[4]  = *(const float4*)&As[kk][64 + ty * 4];
                    *(float4*)&bb[0] = *(const float4*)&Bs[kk][tx * 4];
                    *(float4*)&bb[4] = *(const float4*)&Bs[kk][64 + tx * 4];
#pragma unroll
                    for (int i = 0; i < 8; i++)
#pragma unroll
                        for (int j = 0; j < 8; j++)
                            acc[i][j] = fmaf(a[i], bb[j], acc[i][j]);
                }
                __syncthreads();
            }
#pragma unroll
            for (int i = 0; i < 8; i++) {
                int r = (i < 4) ? (ty * 4 + i) : (64 + ty * 4 + i - 4);
                float* pr = g_part + (size_t)r * (8 * G4) + kc * G4 + cg * 128;
#pragma unroll
                for (int j = 0; j < 8; j++) {
                    int cix = (j < 4) ? (tx * 4 + j) : (64 + tx * 4 + j - 4);
                    pr[cix] = acc[i][j];
                }
            }
        }
        gridbar();
        // ---------------- phase 2: per-batch LSTM + attention ----------------
        {
            const bool active = lengths[b] > t;
            const float* hc = g_hbuf[cur] + (size_t)b * DD;
            float* hn = g_hbuf[cur ^ 1] + (size_t)b * DD;
            float* mm = g_mstate + (size_t)b * DD;
            const float* gx = g_gatesx + (size_t)(b * TT + t) * G4;
            const float* pp = g_part + (size_t)b * (8 * G4);
            for (int d = tid; d < DD; d += 256) {
                float gi = gx[d]        + b_hh[d];
                float gf = gx[512 + d]  + b_hh[512 + d];
                float gg = gx[1024 + d] + b_hh[1024 + d];
                float go = gx[1536 + d] + b_hh[1536 + d];
#pragma unroll
                for (int q = 0; q < 8; q++) {
                    const float* p = pp + q * G4;
                    gi += p[d]; gf += p[512 + d]; gg += p[1024 + d]; go += p[1536 + d];
                }
                float ig = 1.f / (1.f + expf(-gi));
                float fg = 1.f / (1.f + expf(-gf));
                float og = 1.f / (1.f + expf(-go));
                float gt = tanhf(gg);
                float mo = mm[d];
                float mn = fg * mo + ig * gt;
                float hv = og * tanhf(mn);
                if (!active) { mn = mo; hv = hc[d]; }
                mm[d] = mn;
                hn[d] = hv;
                sh_h[d] = hv;
            }
            __syncthreads();
            if (active) {  // uniform branch per CTA
                for (int k = wid; k < KK_; k += 8) {
                    const float* wr = Wg + (size_t)k * DD;
                    float s = 0.f;
                    for (int q = lane; q < DD; q += 32) s = fmaf(wr[q], sh_h[q], s);
#pragma unroll
                    for (int o = 16; o; o >>= 1) s += __shfl_xor_sync(0xffffffffu, s, o);
                    if (lane == 0) sh_gh[k] = s + bg[k];
                }
                __syncthreads();
                for (int k = wid; k < KK_; k += 8) {
                    const float* vp = g_vproj + (size_t)(b * KK_ + k) * KK_;
                    float s = 0.f;
                    for (int q = lane; q < KK_; q += 32) s += tanhf(vp[q] + sh_gh[q]) * wh[q];
#pragma unroll
                    for (int o = 16; o; o >>= 1) s += __shfl_xor_sync(0xffffffffu, s, o);
                    if (lane == 0) sh_z[k] = s + bh0;
                }
                __syncthreads();
                if (wid == 0) {
                    float mx = -3.0e38f;
                    for (int k = lane; k < KK_; k += 32) mx = fmaxf(mx, sh_z[k]);
#pragma unroll
                    for (int o = 16; o; o >>= 1) mx = fmaxf(mx, __shfl_xor_sync(0xffffffffu, mx, o));
                    float sm = 0.f;
                    for (int k = lane; k < KK_; k += 32) { float e = expf(sh_z[k] - mx); sh_alpha[k] = e; sm += e; }
#pragma unroll
                    for (int o = 16; o; o >>= 1) sm += __shfl_xor_sync(0xffffffffu, sm, o);
                    float inv = 1.f / sm;
                    for (int k = lane; k < KK_; k += 32) sh_alpha[k] *= inv;
                }
                __syncthreads();
                float* so = g_s + (size_t)(b * TT + t) * DD;
                const float* sp = spatial + (size_t)b * KK_ * DD;
                for (int d = tid; d < DD; d += 256) {
                    float cc = 0.f;
#pragma unroll
                    for (int k = 0; k < KK_; k++) cc = fmaf(sh_alpha[k], sp[(size_t)k * DD + d], cc);
                    so[d] = cc + sh_h[d];
                }
            }
        }
        gridbar();
        cur ^= 1;
    }
}

// -------------------- launch --------------------
extern "C" void kernel_launch(void* const* d_in, const int* in_sizes, int n_in,
                              void* d_out, int out_size)
{
    const float* spatial      = (const float*)d_in[0];
    const float* global_feats = (const float*)d_in[1];
    const int*   captions     = (const int*)d_in[2];
    const int*   lengths      = (const int*)d_in[3];
    const float* emb          = (const float*)d_in[4];
    const float* W_init_h     = (const float*)d_in[5];
    const float* b_init_h     = (const float*)d_in[6];
    const float* W_init_m     = (const float*)d_in[7];
    const float* b_init_m     = (const float*)d_in[8];
    const float* W_ih         = (const float*)d_in[9];
    const float* b_ih         = (const float*)d_in[10];
    const float* W_hh         = (const float*)d_in[11];
    const float* b_hh         = (const float*)d_in[12];
    const float* Wv           = (const float*)d_in[13];
    const float* bv           = (const float*)d_in[14];
    const float* Wg           = (const float*)d_in[15];
    const float* bg           = (const float*)d_in[16];
    const float* wh           = (const float*)d_in[17];
    const float* bh_att       = (const float*)d_in[18];
    const float* Wp           = (const float*)d_in[19];
    const float* bp           = (const float*)d_in[20];
    float* out = (float*)d_out;

    float *p_embseq, *p_hbuf, *p_m, *p_gxg, *p_gatesx, *p_vproj, *p_s;
    cudaGetSymbolAddress((void**)&p_embseq, g_embseq);
    cudaGetSymbolAddress((void**)&p_hbuf,   g_hbuf);
    cudaGetSymbolAddress((void**)&p_m,      g_mstate);
    cudaGetSymbolAddress((void**)&p_gxg,    g_gxg);
    cudaGetSymbolAddress((void**)&p_gatesx, g_gatesx);
    cudaGetSymbolAddress((void**)&p_vproj,  g_vproj);
    cudaGetSymbolAddress((void**)&p_s,      g_s);

    // 1. gather caption embeddings -> [B*T, E]
    gather_emb<<<(BQ * TT * (EE / 4) + 255) / 256, 256>>>(captions, emb, p_embseq);

    // 2. h0 = global @ W_init_h^T + b_init_h   -> g_hbuf[0]
    gemm_bf3<<<dim3(4, 1), 256>>>(global_feats, DD, W_init_h, DD, p_hbuf, DD,
                                  BQ, DD, DD, b_init_h, nullptr, 1, 0, nullptr, 1);
    // 3. m0 = global @ W_init_m^T + b_init_m   -> g_mstate
    gemm_bf3<<<dim3(4, 1), 256>>>(global_feats, DD, W_init_m, DD, p_m, DD,
                                  BQ, DD, DD, b_init_m, nullptr, 1, 0, nullptr, 1);
    // 4. gxg = global @ W_ih[:,E:]^T + b_ih    -> [B, 4D]
    gemm_bf3<<<dim3(16, 1), 256>>>(global_feats, DD, W_ih + EE, EE + DD, p_gxg, G4,
                                   BQ, G4, DD, b_ih, nullptr, 1, 0, nullptr, 1);
    // 5. gates_x = embseq @ W_ih[:,:E]^T + gxg[b]  -> [B*T, 4D]
    gemm_bf3<<<dim3(16, 20), 256>>>(p_embseq, EE, W_ih, EE + DD, p_gatesx, G4,
                                    BQ * TT, G4, EE, nullptr, p_gxg, TT, G4, nullptr, 1);
    // 6. vproj = spatial @ Wv^T + bv           -> [B*K, K]
    gemm_bf3<<<dim3(1, 49), 256>>>(spatial, DD, Wv, DD, p_vproj, KK_,
                                   BQ * KK_, KK_, DD, bv, nullptr, 1, 0, nullptr, 1);
    // 7. sequential recurrence (persistent, 128 co-resident CTAs)
    recur_kernel<<<128, 256>>>(W_hh, b_hh, lengths, spatial, Wg, bg, wh, bh_att);
    // 8. logits = s @ Wp^T + bp, zeroed where inactive  -> d_out [B*T, V]
    gemm_bf3<<<dim3(79, 20), 256>>>(p_s, DD, Wp, DD, out, VV,
                                    BQ * TT, VV, DD, bp, nullptr, 1, 0, lengths, TT);
}

// round 3
// speedup vs baseline: 1.7168x; 1.3745x over previous
#include <cuda_runtime.h>
#include <cuda_bf16.h>
#include <math.h>
#include <stdint.h>

#define BQ  128
#define KK_ 49
#define DD  512
#define EE  256
#define VV  10000
#define TT  20
#define G4  2048
typedef __nv_bfloat16 bf16;

// -------------------- device scratch (static) --------------------
__device__ __align__(128) bf16 g_embhi[BQ*TT*EE], g_emblo[BQ*TT*EE];
__device__ __align__(128) bf16 g_glhi[BQ*DD],     g_gllo[BQ*DD];
__device__ __align__(128) bf16 g_wihehi[G4*EE],   g_wihelo[G4*EE];
__device__ __align__(128) bf16 g_wihdhi[G4*DD],   g_wihdlo[G4*DD];
__device__ __align__(128) bf16 g_wh_hi[DD*DD],    g_wh_lo[DD*DD];
__device__ __align__(128) bf16 g_wm_hi[DD*DD],    g_wm_lo[DD*DD];
__device__ __align__(128) bf16 g_whhhi[G4*DD],    g_whhlo[G4*DD];
__device__ __align__(128) bf16 g_wvhi[KK_*DD],    g_wvlo[KK_*DD];
__device__ __align__(128) bf16 g_wphi[VV*DD],     g_wplo[VV*DD];
__device__ __align__(128) bf16 g_sphi[BQ*KK_*DD], g_splo[BQ*KK_*DD];
__device__ __align__(128) bf16 g_hhi[BQ*DD],      g_hlo[BQ*DD];
__device__ __align__(128) bf16 g_shi[BQ*TT*DD],   g_slo[BQ*TT*DD];
__device__ __align__(128) float g_hbuf[2][BQ*DD];
__device__ __align__(128) float g_mstate[BQ*DD];
__device__ __align__(128) float g_gxg[BQ*G4];
__device__ __align__(128) float g_gatesx[BQ*TT*G4];
__device__ __align__(128) float g_vproj[BQ*KK_*KK_];
__device__ __align__(128) float g_part[BQ*8*G4];
__device__ unsigned g_barcnt = 0, g_bargen = 0;

// -------------------- helpers --------------------
__device__ __forceinline__ uint32_t su(const void* p) {
    return (uint32_t)__cvta_generic_to_shared(p);
}
__device__ __forceinline__ void cpa16(uint32_t sa, const void* ga, uint32_t sz) {
    asm volatile("cp.async.cg.shared.global [%0],[%1],16,%2;\n" :: "r"(sa), "l"(ga), "r"(sz));
}
__device__ __forceinline__ void cpcommit() { asm volatile("cp.async.commit_group;\n"); }
template<int N> __device__ __forceinline__ void cpwait() {
    asm volatile("cp.async.wait_group %0;\n" :: "n"(N));
}
__device__ __forceinline__ void ldsm4(uint32_t* r, uint32_t a) {
    asm volatile("ldmatrix.sync.aligned.m8n8.x4.shared.b16 {%0,%1,%2,%3},[%4];\n"
                 : "=r"(r[0]), "=r"(r[1]), "=r"(r[2]), "=r"(r[3]) : "r"(a));
}
__device__ __forceinline__ void mmab(float* c, const uint32_t* a, uint32_t b0, uint32_t b1) {
    asm volatile(
        "mma.sync.aligned.m16n8k16.row.col.f32.bf16.bf16.f32 "
        "{%0,%1,%2,%3},{%4,%5,%6,%7},{%8,%9},{%0,%1,%2,%3};\n"
        : "+f"(c[0]), "+f"(c[1]), "+f"(c[2]), "+f"(c[3])
        : "r"(a[0]), "r"(a[1]), "r"(a[2]), "r"(a[3]), "r"(b0), "r"(b1));
}
__device__ __forceinline__ void pack4(float4 v, uint2& uh, uint2& ul) {
    bf16 h0 = __float2bfloat16(v.x), h1 = __float2bfloat16(v.y);
    bf16 h2 = __float2bfloat16(v.z), h3 = __float2bfloat16(v.w);
    bf16 l0 = __float2bfloat16(v.x - __bfloat162float(h0));
    bf16 l1 = __float2bfloat16(v.y - __bfloat162float(h1));
    bf16 l2 = __float2bfloat16(v.z - __bfloat162float(h2));
    bf16 l3 = __float2bfloat16(v.w - __bfloat162float(h3));
    uh.x = ((uint32_t)__bfloat16_as_ushort(h1) << 16) | __bfloat16_as_ushort(h0);
    uh.y = ((uint32_t)__bfloat16_as_ushort(h3) << 16) | __bfloat16_as_ushort(h2);
    ul.x = ((uint32_t)__bfloat16_as_ushort(l1) << 16) | __bfloat16_as_ushort(l0);
    ul.y = ((uint32_t)__bfloat16_as_ushort(l3) << 16) | __bfloat16_as_ushort(l2);
}

// one k16 step of a 128x128 warp-tiled bf16x3 MMA; STR = smem row stride (bf16 elems)
template<int STR>
__device__ __forceinline__ void mma_tile_k16(
    const bf16* A_h, const bf16* A_l, const bf16* B_h, const bf16* B_l,
    int ks, int wm, int wn, int lrow, int lcol, float acc[4][4][4])
{
    uint32_t ah[4][4], al[4][4], bh[2][4], bl[2][4];
#pragma unroll
    for (int mi = 0; mi < 4; mi++) {
        ldsm4(ah[mi], su(A_h + (wm * 64 + mi * 16 + lrow) * STR + ks + lcol));
        ldsm4(al[mi], su(A_l + (wm * 64 + mi * 16 + lrow) * STR + ks + lcol));
    }
#pragma unroll
    for (int p = 0; p < 2; p++) {
        ldsm4(bh[p], su(B_h + (wn * 32 + p * 16 + lrow) * STR + ks + lcol));
        ldsm4(bl[p], su(B_l + (wn * 32 + p * 16 + lrow) * STR + ks + lcol));
    }
#pragma unroll
    for (int mi = 0; mi < 4; mi++)
#pragma unroll
        for (int ni = 0; ni < 4; ni++) {
            const int p = ni >> 1, q = ni & 1;
            mmab(acc[mi][ni], ah[mi], bh[p][q], bh[p][q + 2]);
            mmab(acc[mi][ni], ah[mi], bl[p][q], bl[p][q + 2]);
            mmab(acc[mi][ni], al[mi], bh[p][q], bh[p][q + 2]);
        }
}

// -------------------- split/convert kernel --------------------
struct Seg { const float4* src; uint2* hi; uint2* lo; int srcld4; int lc4; long long start; };
struct SegArr { Seg s[9]; long long total; };

__global__ void split_all(SegArr sa) {
    long long i = (long long)blockIdx.x * blockDim.x + threadIdx.x;
    if (i >= sa.total) return;
    int k = 0;
#pragma unroll
    for (int j = 1; j < 9; j++) if (i >= sa.s[j].start) k = j;
    Seg sg = sa.s[k];
    long long idx = i - sg.start;
    int row = (int)(idx >> sg.lc4);
    int c   = (int)(idx & ((1 << sg.lc4) - 1));
    float4 v = sg.src[(long long)row * sg.srcld4 + c];
    uint2 uh, ul;
    pack4(v, uh, ul);
    sg.hi[idx] = uh;
    sg.lo[idx] = ul;
}

// -------------------- embedding gather (emits bf16 hi/lo) --------------------
__global__ void gather_emb(const int* __restrict__ cap, const float* __restrict__ emb) {
    int i = blockIdx.x * blockDim.x + threadIdx.x;
    if (i >= BQ * TT * (EE / 4)) return;
    int m = i >> 6, e4 = i & 63;
    int tok = cap[m];
    float4 v = reinterpret_cast<const float4*>(emb)[(size_t)tok * 64 + e4];
    uint2 uh, ul;
    pack4(v, uh, ul);
    reinterpret_cast<uint2*>(g_embhi)[(size_t)m * 64 + e4] = uh;
    reinterpret_cast<uint2*>(g_emblo)[(size_t)m * 64 + e4] = ul;
}

// -------------------- pipelined bf16x3 GEMM --------------------
// C[M,N] = A @ B^T (+bias +rowAdd, row mask, optional bf16 hi/lo copy of C)
#define SST   40
#define SMATB (128 * SST)      // elems per matrix tile

__device__ __forceinline__ void gemm_issue(
    bf16* smbase,
    const bf16* __restrict__ Ah, const bf16* __restrict__ Al, int lda,
    const bf16* __restrict__ Bh, const bf16* __restrict__ Bl, int ldb,
    int bm, int bn, int N, int k0, int ldrow, int ldch)
{
    size_t aoff = (size_t)(bm + ldrow) * lda + k0 + ldch * 8;
    uint32_t sa = su(smbase + ldrow * SST + ldch * 8);
    cpa16(sa, Ah + aoff, 16);
    cpa16(sa + 16, Ah + aoff + 8, 16);
    uint32_t sa2 = sa + SMATB * 2;
    cpa16(sa2, Al + aoff, 16);
    cpa16(sa2 + 16, Al + aoff + 8, 16);

    int gn = bn + ldrow;
    uint32_t sz = (gn < N) ? 16u : 0u;
    int gnc = (gn < N) ? gn : 0;
    size_t boff = (size_t)gnc * ldb + k0 + ldch * 8;
    uint32_t sb = sa + 2 * SMATB * 2;
    cpa16(sb, Bh + boff, sz);
    cpa16(sb + 16, Bh + boff + 8, sz);
    uint32_t sb2 = sb + SMATB * 2;
    cpa16(sb2, Bl + boff, sz);
    cpa16(sb2 + 16, Bl + boff + 8, sz);
}

__global__ __launch_bounds__(256) void gemm_hl(
    const bf16* __restrict__ Ah, const bf16* __restrict__ Al, int lda,
    const bf16* __restrict__ Bh, const bf16* __restrict__ Bl, int ldb,
    float* __restrict__ C, int ldc, int M, int N, int K,
    const float* __restrict__ bias,
    const float* __restrict__ rowAdd, int rowDiv, int ldra,
    const int* __restrict__ mlen, int maskT,
    bf16* __restrict__ Chi, bf16* __restrict__ Clo)
{
    extern __shared__ __align__(16) char smraw[];
    bf16* sm = (bf16*)smraw;                     // [2][4][SMATB]

    const int tid = threadIdx.x;
    const int bm = blockIdx.y * 128, bn = blockIdx.x * 128;
    const int w = tid >> 5, lane = tid & 31;
    const int wm = w >> 2, wn = w & 3;
    const int g = lane >> 2, tg = lane & 3;
    const int lrow = lane & 15, lcol = (lane >> 4) * 8;
    const int ldrow = tid >> 1, ldch = (tid & 1) * 2;

    float acc[4][4][4];
#pragma unroll
    for (int i = 0; i < 4; i++)
#pragma unroll
        for (int j = 0; j < 4; j++)
#pragma unroll
            for (int q = 0; q < 4; q++) acc[i][j][q] = 0.f;

    const int niter = K / 32;
    gemm_issue(sm, Ah, Al, lda, Bh, Bl, ldb, bm, bn, N, 0, ldrow, ldch);
    cpcommit();
    int st = 0;
    for (int it = 0; it < niter; ++it) {
        if (it + 1 < niter) {
            gemm_issue(sm + (st ^ 1) * 4 * SMATB, Ah, Al, lda, Bh, Bl, ldb,
                       bm, bn, N, (it + 1) * 32, ldrow, ldch);
            cpcommit();
            cpwait<1>();
        } else {
            cpwait<0>();
        }
        __syncthreads();
        const bf16* base = sm + st * 4 * SMATB;
#pragma unroll
        for (int ks = 0; ks < 32; ks += 16)
            mma_tile_k16<SST>(base, base + SMATB, base + 2 * SMATB, base + 3 * SMATB,
                              ks, wm, wn, lrow, lcol, acc);
        __syncthreads();
        st ^= 1;
    }

    // epilogue
#pragma unroll
    for (int mi = 0; mi < 4; mi++)
#pragma unroll
        for (int ni = 0; ni < 4; ni++) {
            int gn0 = bn + wn * 32 + ni * 8 + tg * 2;
#pragma unroll
            for (int half = 0; half < 2; half++) {
                int gm = bm + wm * 64 + mi * 16 + g + half * 8;
                if (gm >= M) continue;
                bool zero = mlen ? (mlen[gm / maskT] <= (gm % maskT)) : false;
                const float* ra = rowAdd ? (rowAdd + (size_t)(gm / rowDiv) * ldra) : nullptr;
#pragma unroll
                for (int q = 0; q < 2; q++) {
                    int gn = gn0 + q;
                    if (gn >= N) continue;
                    float v = acc[mi][ni][half * 2 + q];
                    if (bias) v += bias[gn];
                    if (ra)   v += ra[gn];
                    if (zero) v = 0.f;
                    C[(size_t)gm * ldc + gn] = v;
                    if (Chi) {
                        bf16 hv = __float2bfloat16(v);
                        Chi[(size_t)gm * ldc + gn] = hv;
                        Clo[(size_t)gm * ldc + gn] = __float2bfloat16(v - __bfloat162float(hv));
                    }
                }
            }
        }
}

// -------------------- grid barrier --------------------
__device__ __forceinline__ void gridbar() {
    __syncthreads();
    if (threadIdx.x == 0) {
        unsigned g = *(volatile unsigned*)&g_bargen;
        __threadfence();
        if (atomicAdd(&g_barcnt, 1u) == gridDim.x - 1) {
            g_barcnt = 0;
            __threadfence();
            atomicExch(&g_bargen, g + 1u);
        } else {
            while (*(volatile unsigned*)&g_bargen == g) { __nanosleep(40); }
        }
        __threadfence();
    }
    __syncthreads();
}

// -------------------- persistent recurrence kernel --------------------
#define RST 72
#define RMATB (128 * RST)

__global__ __launch_bounds__(256, 1) void recur_kernel(
    const float* __restrict__ b_hh,
    const int*   __restrict__ lengths,
    const float* __restrict__ spatial,
    const float* __restrict__ Wg,
    const float* __restrict__ bg,
    const float* __restrict__ wh,
    const float* __restrict__ bh_att)
{
    extern __shared__ __align__(16) char dsm[];
    bf16* sAh = (bf16*)dsm;
    bf16* sAl = sAh + RMATB;
    bf16* sBh = sAl + RMATB;
    bf16* sBl = sBh + RMATB;
    float* sh_h    = (float*)(dsm + 4 * RMATB * 2);
    float* sh_gh   = sh_h + DD;
    float* sh_z    = sh_gh + 52;
    float* sh_alpha= sh_z + 52;

    const int c = blockIdx.x;
    const int tid = threadIdx.x;
    const int kc = c & 7, cg = c >> 3, kbase = kc * 64;
    const int b = c;
    const int w = tid >> 5, lane = tid & 31;
    const int wm = w >> 2, wn = w & 3;
    const int g = lane >> 2, tg = lane & 3;
    const int lrow = lane & 15, lcol = (lane >> 4) * 8;
    const int wid = w;
    const float bh0 = bh_att[0];
    int cur = 0;

    // preload time-invariant W_hh slice (hi/lo) once
#pragma unroll
    for (int j = 0; j < 4; j++) {
        int cid = tid + j * 256;
        int row = cid >> 3, ch = cid & 7;
        *(float4*)(sBh + row * RST + ch * 8) =
            *(const float4*)(g_whhhi + (size_t)(cg * 128 + row) * DD + kbase + ch * 8);
        *(float4*)(sBl + row * RST + ch * 8) =
            *(const float4*)(g_whhlo + (size_t)(cg * 128 + row) * DD + kbase + ch * 8);
    }

    for (int t = 0; t < TT; t++) {
        // ---------------- phase 1: gates = h @ W_hh^T (split-K via kc) ----------------
        {
#pragma unroll
            for (int j = 0; j < 4; j++) {
                int cid = tid + j * 256;
                int row = cid >> 3, ch = cid & 7;
                *(float4*)(sAh + row * RST + ch * 8) =
                    *(const float4*)(g_hhi + (size_t)row * DD + kbase + ch * 8);
                *(float4*)(sAl + row * RST + ch * 8) =
                    *(const float4*)(g_hlo + (size_t)row * DD + kbase + ch * 8);
            }
            __syncthreads();

            float acc[4][4][4];
#pragma unroll
            for (int i = 0; i < 4; i++)
#pragma unroll
                for (int j = 0; j < 4; j++)
#pragma unroll
                    for (int q = 0; q < 4; q++) acc[i][j][q] = 0.f;

#pragma unroll
            for (int ks = 0; ks < 64; ks += 16)
                mma_tile_k16<RST>(sAh, sAl, sBh, sBl, ks, wm, wn, lrow, lcol, acc);

#pragma unroll
            for (int mi = 0; mi < 4; mi++)
#pragma unroll
                for (int ni = 0; ni < 4; ni++) {
                    int gn0 = wn * 32 + ni * 8 + tg * 2;
#pragma unroll
                    for (int half = 0; half < 2; half++) {
                        int gm = wm * 64 + mi * 16 + g + half * 8;   // batch row
                        float* pr = g_part + (size_t)gm * (8 * G4) + kc * G4 + cg * 128 + gn0;
                        pr[0] = acc[mi][ni][half * 2 + 0];
                        pr[1] = acc[mi][ni][half * 2 + 1];
                    }
                }
        }
        gridbar();
        // ---------------- phase 2: per-batch LSTM + attention ----------------
        {
            const bool active = lengths[b] > t;
            const float* hc = g_hbuf[cur] + (size_t)b * DD;
            float* hn = g_hbuf[cur ^ 1] + (size_t)b * DD;
            float* mm = g_mstate + (size_t)b * DD;
            const float* gx = g_gatesx + (size_t)(b * TT + t) * G4;
            const float* pp = g_part + (size_t)b * (8 * G4);
            for (int d = tid; d < DD; d += 256) {
                float gi = gx[d]        + b_hh[d];
                float gf = gx[512 + d]  + b_hh[512 + d];
                float gg = gx[1024 + d] + b_hh[1024 + d];
                float go = gx[1536 + d] + b_hh[1536 + d];
#pragma unroll
                for (int q = 0; q < 8; q++) {
                    const float* p = pp + q * G4;
                    gi += p[d]; gf += p[512 + d]; gg += p[1024 + d]; go += p[1536 + d];
                }
                float ig = 1.f / (1.f + expf(-gi));
                float fg = 1.f / (1.f + expf(-gf));
                float og = 1.f / (1.f + expf(-go));
                float gt = tanhf(gg);
                float mo = mm[d];
                float mn = fg * mo + ig * gt;
                float hv = og * tanhf(mn);
                if (!active) { mn = mo; hv = hc[d]; }
                mm[d] = mn;
                hn[d] = hv;
                sh_h[d] = hv;
                bf16 hh = __float2bfloat16(hv);
                g_hhi[(size_t)b * DD + d] = hh;
                g_hlo[(size_t)b * DD + d] = __float2bfloat16(hv - __bfloat162float(hh));
            }
            __syncthreads();
            if (active) {
                for (int k = wid; k < KK_; k += 8) {
                    const float* wr = Wg + (size_t)k * DD;
                    float s = 0.f;
                    for (int q = lane; q < DD; q += 32) s = fmaf(wr[q], sh_h[q], s);
#pragma unroll
                    for (int o = 16; o; o >>= 1) s += __shfl_xor_sync(0xffffffffu, s, o);
                    if (lane == 0) sh_gh[k] = s + bg[k];
                }
                __syncthreads();
                for (int k = wid; k < KK_; k += 8) {
                    const float* vp = g_vproj + (size_t)(b * KK_ + k) * KK_;
                    float s = 0.f;
                    for (int q = lane; q < KK_; q += 32) s += tanhf(vp[q] + sh_gh[q]) * wh[q];
#pragma unroll
                    for (int o = 16; o; o >>= 1) s += __shfl_xor_sync(0xffffffffu, s, o);
                    if (lane == 0) sh_z[k] = s + bh0;
                }
                __syncthreads();
                if (wid == 0) {
                    float mx = -3.0e38f;
                    for (int k = lane; k < KK_; k += 32) mx = fmaxf(mx, sh_z[k]);
#pragma unroll
                    for (int o = 16; o; o >>= 1) mx = fmaxf(mx, __shfl_xor_sync(0xffffffffu, mx, o));
                    float sm = 0.f;
                    for (int k = lane; k < KK_; k += 32) { float e = expf(sh_z[k] - mx); sh_alpha[k] = e; sm += e; }
#pragma unroll
                    for (int o = 16; o; o >>= 1) sm += __shfl_xor_sync(0xffffffffu, sm, o);
                    float inv = 1.f / sm;
                    for (int k = lane; k < KK_; k += 32) sh_alpha[k] *= inv;
                }
                __syncthreads();
                const float* sp = spatial + (size_t)b * KK_ * DD;
                for (int d = tid; d < DD; d += 256) {
                    float cc = 0.f;
#pragma unroll
                    for (int k = 0; k < KK_; k++) cc = fmaf(sh_alpha[k], sp[(size_t)k * DD + d], cc);
                    float sv = cc + sh_h[d];
                    bf16 shh = __float2bfloat16(sv);
                    g_shi[(size_t)(b * TT + t) * DD + d] = shh;
                    g_slo[(size_t)(b * TT + t) * DD + d] = __float2bfloat16(sv - __bfloat162float(shh));
                }
            }
        }
        gridbar();
        cur ^= 1;
    }
}

// -------------------- launch --------------------
extern "C" void kernel_launch(void* const* d_in, const int* in_sizes, int n_in,
                              void* d_out, int out_size)
{
    const float* spatial      = (const float*)d_in[0];
    const float* global_feats = (const float*)d_in[1];
    const int*   captions     = (const int*)d_in[2];
    const int*   lengths      = (const int*)d_in[3];
    const float* emb          = (const float*)d_in[4];
    const float* W_init_h     = (const float*)d_in[5];
    const float* b_init_h     = (const float*)d_in[6];
    const float* W_init_m     = (const float*)d_in[7];
    const float* b_init_m     = (const float*)d_in[8];
    const float* W_ih         = (const float*)d_in[9];
    const float* b_ih         = (const float*)d_in[10];
    const float* W_hh         = (const float*)d_in[11];
    const float* b_hh         = (const float*)d_in[12];
    const float* Wv           = (const float*)d_in[13];
    const float* bv           = (const float*)d_in[14];
    const float* Wg           = (const float*)d_in[15];
    const float* bg           = (const float*)d_in[16];
    const float* wh           = (const float*)d_in[17];
    const float* bh_att       = (const float*)d_in[18];
    const float* Wp           = (const float*)d_in[19];
    const float* bp           = (const float*)d_in[20];
    float* out = (float*)d_out;

#define GETP(var, sym) void* var; cudaGetSymbolAddress(&var, sym)
    GETP(p_embhi, g_embhi);  GETP(p_emblo, g_emblo);
    GETP(p_glhi, g_glhi);    GETP(p_gllo, g_gllo);
    GETP(p_wihehi, g_wihehi);GETP(p_wihelo, g_wihelo);
    GETP(p_wihdhi, g_wihdhi);GETP(p_wihdlo, g_wihdlo);
    GETP(p_whhi, g_wh_hi);   GETP(p_whlo, g_wh_lo);
    GETP(p_wmhi, g_wm_hi);   GETP(p_wmlo, g_wm_lo);
    GETP(p_whhhi, g_whhhi);  GETP(p_whhlo, g_whhlo);
    GETP(p_wvhi, g_wvhi);    GETP(p_wvlo, g_wvlo);
    GETP(p_wphi, g_wphi);    GETP(p_wplo, g_wplo);
    GETP(p_sphi, g_sphi);    GETP(p_splo, g_splo);
    GETP(p_hhi, g_hhi);      GETP(p_hlo, g_hlo);
    GETP(p_shi, g_shi);      GETP(p_slo, g_slo);
    GETP(p_hbuf, g_hbuf);    GETP(p_m, g_mstate);
    GETP(p_gxg, g_gxg);      GETP(p_gatesx, g_gatesx);
    GETP(p_vproj, g_vproj);
#undef GETP

    const int GSM = 2 * 4 * SMATB * 2;                       // 81920 B
    const int RSM = 4 * RMATB * 2 + (DD + 3 * 52) * 4;       // ~76.4 KB
    cudaFuncSetAttribute(gemm_hl, cudaFuncAttributeMaxDynamicSharedMemorySize, GSM);
    cudaFuncSetAttribute(recur_kernel, cudaFuncAttributeMaxDynamicSharedMemorySize, RSM);

    // ---- 1. split all fp32 operands into bf16 hi/lo ----
    SegArr sa;
    long long pos = 0;
    auto seg = [&](int i, const float* src, void* hi, void* lo, int srcld, int cols, int rows) {
        sa.s[i].src = (const float4*)src;
        sa.s[i].hi = (uint2*)hi;  sa.s[i].lo = (uint2*)lo;
        sa.s[i].srcld4 = srcld / 4;
        sa.s[i].lc4 = (cols / 4 == 64) ? 6 : 7;
        sa.s[i].start = pos;
        pos += (long long)rows * (cols / 4);
    };
    seg(0, global_feats, p_glhi, p_gllo, DD, DD, BQ);
    seg(1, W_init_h, p_whhi, p_whlo, DD, DD, DD);
    seg(2, W_init_m, p_wmhi, p_wmlo, DD, DD, DD);
    seg(3, W_ih, p_wihehi, p_wihelo, EE + DD, EE, G4);
    seg(4, W_ih + EE, p_wihdhi, p_wihdlo, EE + DD, DD, G4);
    seg(5, W_hh, p_whhhi, p_whhlo, DD, DD, G4);
    seg(6, Wv, p_wvhi, p_wvlo, DD, DD, KK_);
    seg(7, Wp, p_wphi, p_wplo, DD, DD, VV);
    seg(8, spatial, p_sphi, p_splo, DD, DD, BQ * KK_);
    sa.total = pos;
    split_all<<<(unsigned)((pos + 255) / 256), 256>>>(sa);

    // ---- 2. gather caption embeddings (bf16 hi/lo) ----
    gather_emb<<<(BQ * TT * (EE / 4) + 255) / 256, 256>>>(captions, emb);

    // ---- 3. h0 (also emits bf16 hi/lo of h0) ----
    gemm_hl<<<dim3(4, 1), 256, GSM>>>((bf16*)p_glhi, (bf16*)p_gllo, DD,
        (bf16*)p_whhi, (bf16*)p_whlo, DD, (float*)p_hbuf, DD, BQ, DD, DD,
        b_init_h, nullptr, 1, 0, nullptr, 1, (bf16*)p_hhi, (bf16*)p_hlo);
    // ---- 4. m0 ----
    gemm_hl<<<dim3(4, 1), 256, GSM>>>((bf16*)p_glhi, (bf16*)p_gllo, DD,
        (bf16*)p_wmhi, (bf16*)p_wmlo, DD, (float*)p_m, DD, BQ, DD, DD,
        b_init_m, nullptr, 1, 0, nullptr, 1, nullptr, nullptr);
    // ---- 5. gxg = global @ W_ih[:,E:]^T + b_ih ----
    gemm_hl<<<dim3(16, 1), 256, GSM>>>((bf16*)p_glhi, (bf16*)p_gllo, DD,
        (bf16*)p_wihdhi, (bf16*)p_wihdlo, DD, (float*)p_gxg, G4, BQ, G4, DD,
        b_ih, nullptr, 1, 0, nullptr, 1, nullptr, nullptr);
    // ---- 6. gates_x = embseq @ W_ih[:,:E]^T + gxg[b] ----
    gemm_hl<<<dim3(16, 20), 256, GSM>>>((bf16*)p_embhi, (bf16*)p_emblo, EE,
        (bf16*)p_wihehi, (bf16*)p_wihelo, EE, (float*)p_gatesx, G4, BQ * TT, G4, EE,
        nullptr, (const float*)p_gxg, TT, G4, nullptr, 1, nullptr, nullptr);
    // ---- 7. vproj = spatial @ Wv^T + bv ----
    gemm_hl<<<dim3(1, 49), 256, GSM>>>((bf16*)p_sphi, (bf16*)p_splo, DD,
        (bf16*)p_wvhi, (bf16*)p_wvlo, DD, (float*)p_vproj, KK_, BQ * KK_, KK_, DD,
        bv, nullptr, 1, 0, nullptr, 1, nullptr, nullptr);
    // ---- 8. recurrence ----
    recur_kernel<<<128, 256, RSM>>>(b_hh, lengths, spatial, Wg, bg, wh, bh_att);
    // ---- 9. logits = s @ Wp^T + bp (masked) ----
    gemm_hl<<<dim3(79, 20), 256, GSM>>>((bf16*)p_shi, (bf16*)p_slo, DD,
        (bf16*)p_wphi, (bf16*)p_wplo, DD, out, VV, BQ * TT, VV, DD,
        bp, nullptr, 1, 0, lengths, TT, nullptr, nullptr);
}

// round 4
// speedup vs baseline: 1.9777x; 1.1520x over previous
#include <cuda_runtime.h>
#include <cuda_bf16.h>
#include <math.h>
#include <stdint.h>

#define BQ  128
#define KK_ 49
#define DD  512
#define EE  256
#define VV  10000
#define TT  20
#define G4  2048
typedef __nv_bfloat16 bf16;

// -------------------- device scratch (static) --------------------
__device__ __align__(128) bf16 g_embhi[BQ*TT*EE], g_emblo[BQ*TT*EE];
__device__ __align__(128) bf16 g_glhi[BQ*DD],     g_gllo[BQ*DD];
__device__ __align__(128) bf16 g_wihehi[G4*EE],   g_wihelo[G4*EE];
__device__ __align__(128) bf16 g_wcathi[3072*DD], g_wcatlo[3072*DD];  // [Winit_h;Winit_m;W_ih_D]
__device__ __align__(128) bf16 g_whhhi[G4*DD],    g_whhlo[G4*DD];
__device__ __align__(128) bf16 g_wvhi[KK_*DD],    g_wvlo[KK_*DD];
__device__ __align__(128) bf16 g_wphi[VV*DD],     g_wplo[VV*DD];
__device__ __align__(128) bf16 g_sphi[BQ*KK_*DD], g_splo[BQ*KK_*DD];
__device__ __align__(128) bf16 g_hhi[BQ*DD],      g_hlo[BQ*DD];
__device__ __align__(128) bf16 g_shi[BQ*TT*DD],   g_slo[BQ*TT*DD];
__device__ __align__(128) float g_hbuf[2][BQ*DD];
__device__ __align__(128) float g_mstate[BQ*DD];
__device__ __align__(128) float g_gxg[BQ*G4];
__device__ __align__(128) float g_gatesx[BQ*TT*G4];
__device__ __align__(128) float g_vproj[BQ*KK_*KK_];
__device__ __align__(128) float g_part[BQ*8*G4];
__device__ __align__(128) float g_ipart[4][BQ*3072];      // split-K partials of init GEMM
__device__ __align__(128) float g_vpart[2][BQ*KK_*KK_];   // split-K partials of vproj
__device__ unsigned g_barcnt = 0, g_bargen = 0;

// -------------------- helpers --------------------
__device__ __forceinline__ uint32_t su(const void* p) {
    return (uint32_t)__cvta_generic_to_shared(p);
}
__device__ __forceinline__ void cpa16(uint32_t sa, const void* ga, uint32_t sz) {
    asm volatile("cp.async.cg.shared.global [%0],[%1],16,%2;\n" :: "r"(sa), "l"(ga), "r"(sz));
}
__device__ __forceinline__ void cpcommit() { asm volatile("cp.async.commit_group;\n"); }
template<int N> __device__ __forceinline__ void cpwait() {
    asm volatile("cp.async.wait_group %0;\n" :: "n"(N));
}
__device__ __forceinline__ void ldsm4(uint32_t* r, uint32_t a) {
    asm volatile("ldmatrix.sync.aligned.m8n8.x4.shared.b16 {%0,%1,%2,%3},[%4];\n"
                 : "=r"(r[0]), "=r"(r[1]), "=r"(r[2]), "=r"(r[3]) : "r"(a));
}
__device__ __forceinline__ void mmab(float* c, const uint32_t* a, uint32_t b0, uint32_t b1) {
    asm volatile(
        "mma.sync.aligned.m16n8k16.row.col.f32.bf16.bf16.f32 "
        "{%0,%1,%2,%3},{%4,%5,%6,%7},{%8,%9},{%0,%1,%2,%3};\n"
        : "+f"(c[0]), "+f"(c[1]), "+f"(c[2]), "+f"(c[3])
        : "r"(a[0]), "r"(a[1]), "r"(a[2]), "r"(a[3]), "r"(b0), "r"(b1));
}
__device__ __forceinline__ void pack4(float4 v, uint2& uh, uint2& ul) {
    bf16 h0 = __float2bfloat16(v.x), h1 = __float2bfloat16(v.y);
    bf16 h2 = __float2bfloat16(v.z), h3 = __float2bfloat16(v.w);
    bf16 l0 = __float2bfloat16(v.x - __bfloat162float(h0));
    bf16 l1 = __float2bfloat16(v.y - __bfloat162float(h1));
    bf16 l2 = __float2bfloat16(v.z - __bfloat162float(h2));
    bf16 l3 = __float2bfloat16(v.w - __bfloat162float(h3));
    uh.x = ((uint32_t)__bfloat16_as_ushort(h1) << 16) | __bfloat16_as_ushort(h0);
    uh.y = ((uint32_t)__bfloat16_as_ushort(h3) << 16) | __bfloat16_as_ushort(h2);
    ul.x = ((uint32_t)__bfloat16_as_ushort(l1) << 16) | __bfloat16_as_ushort(l0);
    ul.y = ((uint32_t)__bfloat16_as_ushort(l3) << 16) | __bfloat16_as_ushort(l2);
}
__device__ __forceinline__ float fsig(float x) { return 1.f / (1.f + __expf(-x)); }
__device__ __forceinline__ float ftanh(float x) {
    float e = __expf(2.f * x);
    return 1.f - 2.f / (e + 1.f);
}

// one k16 step of a 128x128 warp-tiled bf16x3 MMA; STR = smem row stride (bf16 elems)
template<int STR>
__device__ __forceinline__ void mma_tile_k16(
    const bf16* A_h, const bf16* A_l, const bf16* B_h, const bf16* B_l,
    int ks, int wm, int wn, int lrow, int lcol, float acc[4][4][4])
{
    uint32_t ah[4][4], al[4][4], bh[2][4], bl[2][4];
#pragma unroll
    for (int mi = 0; mi < 4; mi++) {
        ldsm4(ah[mi], su(A_h + (wm * 64 + mi * 16 + lrow) * STR + ks + lcol));
        ldsm4(al[mi], su(A_l + (wm * 64 + mi * 16 + lrow) * STR + ks + lcol));
    }
#pragma unroll
    for (int p = 0; p < 2; p++) {
        ldsm4(bh[p], su(B_h + (wn * 32 + p * 16 + lrow) * STR + ks + lcol));
        ldsm4(bl[p], su(B_l + (wn * 32 + p * 16 + lrow) * STR + ks + lcol));
    }
#pragma unroll
    for (int mi = 0; mi < 4; mi++)
#pragma unroll
        for (int ni = 0; ni < 4; ni++) {
            const int p = ni >> 1, q = ni & 1;
            mmab(acc[mi][ni], ah[mi], bh[p][q], bh[p][q + 2]);
            mmab(acc[mi][ni], ah[mi], bl[p][q], bl[p][q + 2]);
            mmab(acc[mi][ni], al[mi], bh[p][q], bh[p][q + 2]);
        }
}

// -------------------- split/convert kernel --------------------
struct Seg { const float4* src; uint2* hi; uint2* lo; int srcld4; int lc4; long long start; };
struct SegArr { Seg s[9]; long long total; };

__global__ void split_all(SegArr sa) {
    long long i = (long long)blockIdx.x * blockDim.x + threadIdx.x;
    if (i >= sa.total) return;
    int k = 0;
#pragma unroll
    for (int j = 1; j < 9; j++) if (i >= sa.s[j].start) k = j;
    Seg sg = sa.s[k];
    long long idx = i - sg.start;
    int row = (int)(idx >> sg.lc4);
    int c   = (int)(idx & ((1 << sg.lc4) - 1));
    float4 v = sg.src[(long long)row * sg.srcld4 + c];
    uint2 uh, ul;
    pack4(v, uh, ul);
    sg.hi[idx] = uh;
    sg.lo[idx] = ul;
}

// -------------------- embedding gather (emits bf16 hi/lo) --------------------
__global__ void gather_emb(const int* __restrict__ cap, const float* __restrict__ emb) {
    int i = blockIdx.x * blockDim.x + threadIdx.x;
    if (i >= BQ * TT * (EE / 4)) return;
    int m = i >> 6, e4 = i & 63;
    int tok = cap[m];
    float4 v = reinterpret_cast<const float4*>(emb)[(size_t)tok * 64 + e4];
    uint2 uh, ul;
    pack4(v, uh, ul);
    reinterpret_cast<uint2*>(g_embhi)[(size_t)m * 64 + e4] = uh;
    reinterpret_cast<uint2*>(g_emblo)[(size_t)m * 64 + e4] = ul;
}

// -------------------- pipelined bf16x3 GEMM (optional split-K via blockIdx.z) --------
#define SST   40
#define SMATB (128 * SST)

__device__ __forceinline__ void gemm_issue(
    bf16* smbase,
    const bf16* __restrict__ Ah, const bf16* __restrict__ Al, int lda,
    const bf16* __restrict__ Bh, const bf16* __restrict__ Bl, int ldb,
    int bm, int bn, int N, int k0, int ldrow, int ldch)
{
    size_t aoff = (size_t)(bm + ldrow) * lda + k0 + ldch * 8;
    uint32_t sa = su(smbase + ldrow * SST + ldch * 8);
    cpa16(sa, Ah + aoff, 16);
    cpa16(sa + 16, Ah + aoff + 8, 16);
    uint32_t sa2 = sa + SMATB * 2;
    cpa16(sa2, Al + aoff, 16);
    cpa16(sa2 + 16, Al + aoff + 8, 16);

    int gn = bn + ldrow;
    uint32_t sz = (gn < N) ? 16u : 0u;
    int gnc = (gn < N) ? gn : 0;
    size_t boff = (size_t)gnc * ldb + k0 + ldch * 8;
    uint32_t sb = sa + 2 * SMATB * 2;
    cpa16(sb, Bh + boff, sz);
    cpa16(sb + 16, Bh + boff + 8, sz);
    uint32_t sb2 = sb + SMATB * 2;
    cpa16(sb2, Bl + boff, sz);
    cpa16(sb2 + 16, Bl + boff + 8, sz);
}

__global__ void __launch_bounds__(256, 2) gemm_hl(
    const bf16* __restrict__ Ah, const bf16* __restrict__ Al, int lda,
    const bf16* __restrict__ Bh, const bf16* __restrict__ Bl, int ldb,
    float* __restrict__ C, int ldc, int M, int N, int K,   // K = per-z slice length
    const float* __restrict__ bias,
    const int* __restrict__ mlen, int maskT,
    float* __restrict__ Cpart, long partStride)
{
    extern __shared__ __align__(16) char smraw[];
    bf16* sm = (bf16*)smraw;                     // [2][4][SMATB]

    const int tid = threadIdx.x;
    const int bm = blockIdx.y * 128, bn = blockIdx.x * 128;
    const int kz = blockIdx.z;
    const bf16* Ahz = Ah + (size_t)kz * K;
    const bf16* Alz = Al + (size_t)kz * K;
    const bf16* Bhz = Bh + (size_t)kz * K;
    const bf16* Blz = Bl + (size_t)kz * K;
    float* Cw = Cpart ? (Cpart + (size_t)kz * partStride) : C;

    const int w = tid >> 5, lane = tid & 31;
    const int wm = w >> 2, wn = w & 3;
    const int g = lane >> 2, tg = lane & 3;
    const int lrow = lane & 15, lcol = (lane >> 4) * 8;
    const int ldrow = tid >> 1, ldch = (tid & 1) * 2;

    float acc[4][4][4];
#pragma unroll
    for (int i = 0; i < 4; i++)
#pragma unroll
        for (int j = 0; j < 4; j++)
#pragma unroll
            for (int q = 0; q < 4; q++) acc[i][j][q] = 0.f;

    const int niter = K / 32;
    gemm_issue(sm, Ahz, Alz, lda, Bhz, Blz, ldb, bm, bn, N, 0, ldrow, ldch);
    cpcommit();
    int st = 0;
    for (int it = 0; it < niter; ++it) {
        if (it + 1 < niter) {
            gemm_issue(sm + (st ^ 1) * 4 * SMATB, Ahz, Alz, lda, Bhz, Blz, ldb,
                       bm, bn, N, (it + 1) * 32, ldrow, ldch);
            cpcommit();
            cpwait<1>();
        } else {
            cpwait<0>();
        }
        __syncthreads();
        const bf16* base = sm + st * 4 * SMATB;
#pragma unroll
        for (int ks = 0; ks < 32; ks += 16)
            mma_tile_k16<SST>(base, base + SMATB, base + 2 * SMATB, base + 3 * SMATB,
                              ks, wm, wn, lrow, lcol, acc);
        __syncthreads();
        st ^= 1;
    }

    // epilogue
#pragma unroll
    for (int mi = 0; mi < 4; mi++)
#pragma unroll
        for (int ni = 0; ni < 4; ni++) {
            int gn0 = bn + wn * 32 + ni * 8 + tg * 2;
#pragma unroll
            for (int half = 0; half < 2; half++) {
                int gm = bm + wm * 64 + mi * 16 + g + half * 8;
                if (gm >= M) continue;
                bool zero = mlen ? (mlen[gm / maskT] <= (gm % maskT)) : false;
#pragma unroll
                for (int q = 0; q < 2; q++) {
                    int gn = gn0 + q;
                    if (gn >= N) continue;
                    float v = acc[mi][ni][half * 2 + q];
                    if (bias) v += bias[gn];
                    if (zero) v = 0.f;
                    Cw[(size_t)gm * ldc + gn] = v;
                }
            }
        }
}

// -------------------- cheap grid barrier (acq/rel, no fences) --------------------
__device__ __forceinline__ void gridbar() {
    __syncthreads();
    if (threadIdx.x == 0) {
        unsigned gen = *(volatile unsigned*)&g_bargen;
        unsigned old;
        asm volatile("atom.add.release.gpu.u32 %0,[%1],1;"
                     : "=r"(old) : "l"(&g_barcnt) : "memory");
        if (old == gridDim.x - 1) {
            g_barcnt = 0;
            asm volatile("st.release.gpu.u32 [%0],%1;"
                         :: "l"(&g_bargen), "r"(gen + 1) : "memory");
        } else {
            unsigned v;
            do {
                asm volatile("ld.acquire.gpu.u32 %0,[%1];"
                             : "=r"(v) : "l"(&g_bargen) : "memory");
            } while (v == gen);
        }
    }
    __syncthreads();
}

// -------------------- persistent recurrence kernel --------------------
#define RST 72
#define RMATB (128 * RST)

__global__ __launch_bounds__(256, 1) void recur_kernel(
    const float* __restrict__ b_hh,
    const int*   __restrict__ lengths,
    const float* __restrict__ spatial,
    const float* __restrict__ Wg,
    const float* __restrict__ bg,
    const float* __restrict__ wh,
    const float* __restrict__ bh_att,
    const float* __restrict__ b_init_h,
    const float* __restrict__ b_init_m,
    const float* __restrict__ b_ih,
    const float* __restrict__ bv)
{
    extern __shared__ __align__(16) char dsm[];
    bf16* sAh = (bf16*)dsm;
    bf16* sAl = sAh + RMATB;
    bf16* sBh = sAl + RMATB;
    bf16* sBl = sBh + RMATB;
    float* sh_h    = (float*)(dsm + 4 * RMATB * 2);
    float* sh_gh   = sh_h + DD;
    float* sh_z    = sh_gh + 52;
    float* sh_alpha= sh_z + 52;

    const int c = blockIdx.x;
    const int tid = threadIdx.x;
    const int kc = c & 7, cg = c >> 3, kbase = kc * 64;
    const int b = c;
    const int w = tid >> 5, lane = tid & 31;
    const int wm = w >> 2, wn = w & 3;
    const int g = lane >> 2, tg = lane & 3;
    const int lrow = lane & 15, lcol = (lane >> 4) * 8;
    const int wid = w;
    const float bh0 = bh_att[0];
    int cur = 0;

    // ---- prologue A: inline reduce of init split-K partials for batch b ----
    for (int n = tid; n < 3072; n += 256) {
        float v = g_ipart[0][b * 3072 + n] + g_ipart[1][b * 3072 + n]
                + g_ipart[2][b * 3072 + n] + g_ipart[3][b * 3072 + n];
        if (n < 512) {
            v += b_init_h[n];
            g_hbuf[0][b * DD + n] = v;
            bf16 hh = __float2bfloat16(v);
            g_hhi[b * DD + n] = hh;
            g_hlo[b * DD + n] = __float2bfloat16(v - __bfloat162float(hh));
        } else if (n < 1024) {
            g_mstate[b * DD + (n - 512)] = v + b_init_m[n - 512];
        } else {
            g_gxg[b * G4 + (n - 1024)] = v + b_ih[n - 1024];
        }
    }
    // ---- prologue B: inline reduce of vproj split-K partials for batch b ----
    for (int i = tid; i < KK_ * KK_; i += 256) {
        int r = b * KK_ + i / KK_, q = i % KK_;
        g_vproj[(size_t)r * KK_ + q] =
            g_vpart[0][(size_t)r * KK_ + q] + g_vpart[1][(size_t)r * KK_ + q] + bv[q];
    }
    // ---- prologue C: preload time-invariant W_hh slice (hi/lo) ----
#pragma unroll
    for (int j = 0; j < 4; j++) {
        int cid = tid + j * 256;
        int row = cid >> 3, ch = cid & 7;
        *(float4*)(sBh + row * RST + ch * 8) =
            *(const float4*)(g_whhhi + (size_t)(cg * 128 + row) * DD + kbase + ch * 8);
        *(float4*)(sBl + row * RST + ch * 8) =
            *(const float4*)(g_whhlo + (size_t)(cg * 128 + row) * DD + kbase + ch * 8);
    }
    gridbar();   // h0 hi/lo must be visible to all CTAs

    for (int t = 0; t < TT; t++) {
        // ---------------- phase 1: gates = h @ W_hh^T (split-K via kc) ----------------
        {
#pragma unroll
            for (int j = 0; j < 4; j++) {
                int cid = tid + j * 256;
                int row = cid >> 3, ch = cid & 7;
                *(float4*)(sAh + row * RST + ch * 8) =
                    *(const float4*)(g_hhi + (size_t)row * DD + kbase + ch * 8);
                *(float4*)(sAl + row * RST + ch * 8) =
                    *(const float4*)(g_hlo + (size_t)row * DD + kbase + ch * 8);
            }
            __syncthreads();

            float acc[4][4][4];
#pragma unroll
            for (int i = 0; i < 4; i++)
#pragma unroll
                for (int j = 0; j < 4; j++)
#pragma unroll
                    for (int q = 0; q < 4; q++) acc[i][j][q] = 0.f;

#pragma unroll
            for (int ks = 0; ks < 64; ks += 16)
                mma_tile_k16<RST>(sAh, sAl, sBh, sBl, ks, wm, wn, lrow, lcol, acc);

#pragma unroll
            for (int mi = 0; mi < 4; mi++)
#pragma unroll
                for (int ni = 0; ni < 4; ni++) {
                    int gn0 = wn * 32 + ni * 8 + tg * 2;
#pragma unroll
                    for (int half = 0; half < 2; half++) {
                        int gm = wm * 64 + mi * 16 + g + half * 8;   // batch row
                        float* pr = g_part + (size_t)gm * (8 * G4) + kc * G4 + cg * 128 + gn0;
                        pr[0] = acc[mi][ni][half * 2 + 0];
                        pr[1] = acc[mi][ni][half * 2 + 1];
                    }
                }
        }
        gridbar();
        // ---------------- phase 2: per-batch LSTM + attention ----------------
        {
            const bool active = lengths[b] > t;
            const float* hc = g_hbuf[cur] + (size_t)b * DD;
            float* hn = g_hbuf[cur ^ 1] + (size_t)b * DD;
            float* mm = g_mstate + (size_t)b * DD;
            const float* gx  = g_gatesx + (size_t)(b * TT + t) * G4;
            const float* gxg = g_gxg + (size_t)b * G4;
            const float* pp = g_part + (size_t)b * (8 * G4);
            for (int d = tid; d < DD; d += 256) {
                float gi = gx[d]        + gxg[d]        + b_hh[d];
                float gf = gx[512 + d]  + gxg[512 + d]  + b_hh[512 + d];
                float gg = gx[1024 + d] + gxg[1024 + d] + b_hh[1024 + d];
                float go = gx[1536 + d] + gxg[1536 + d] + b_hh[1536 + d];
#pragma unroll
                for (int q = 0; q < 8; q++) {
                    const float* p = pp + q * G4;
                    gi += p[d]; gf += p[512 + d]; gg += p[1024 + d]; go += p[1536 + d];
                }
                float ig = fsig(gi), fg = fsig(gf), og = fsig(go);
                float gt = ftanh(gg);
                float mo = mm[d];
                float mn = fg * mo + ig * gt;
                float hv = og * ftanh(mn);
                if (!active) { mn = mo; hv = hc[d]; }
                mm[d] = mn;
                hn[d] = hv;
                sh_h[d] = hv;
                bf16 hh = __float2bfloat16(hv);
                g_hhi[(size_t)b * DD + d] = hh;
                g_hlo[(size_t)b * DD + d] = __float2bfloat16(hv - __bfloat162float(hh));
            }
            __syncthreads();
            if (active) {
                for (int k = wid; k < KK_; k += 8) {
                    const float* wr = Wg + (size_t)k * DD;
                    float s = 0.f;
                    for (int q = lane; q < DD; q += 32) s = fmaf(wr[q], sh_h[q], s);
#pragma unroll
                    for (int o = 16; o; o >>= 1) s += __shfl_xor_sync(0xffffffffu, s, o);
                    if (lane == 0) sh_gh[k] = s + bg[k];
                }
                __syncthreads();
                for (int k = wid; k < KK_; k += 8) {
                    const float* vp = g_vproj + (size_t)(b * KK_ + k) * KK_;
                    float s = 0.f;
                    for (int q = lane; q < KK_; q += 32) s += ftanh(vp[q] + sh_gh[q]) * wh[q];
#pragma unroll
                    for (int o = 16; o; o >>= 1) s += __shfl_xor_sync(0xffffffffu, s, o);
                    if (lane == 0) sh_z[k] = s + bh0;
                }
                __syncthreads();
                if (wid == 0) {
                    float mx = -3.0e38f;
                    for (int k = lane; k < KK_; k += 32) mx = fmaxf(mx, sh_z[k]);
#pragma unroll
                    for (int o = 16; o; o >>= 1) mx = fmaxf(mx, __shfl_xor_sync(0xffffffffu, mx, o));
                    float sm = 0.f;
                    for (int k = lane; k < KK_; k += 32) { float e = __expf(sh_z[k] - mx); sh_alpha[k] = e; sm += e; }
#pragma unroll
                    for (int o = 16; o; o >>= 1) sm += __shfl_xor_sync(0xffffffffu, sm, o);
                    float inv = 1.f / sm;
                    for (int k = lane; k < KK_; k += 32) sh_alpha[k] *= inv;
                }
                __syncthreads();
                const float* sp = spatial + (size_t)b * KK_ * DD;
                for (int d = tid; d < DD; d += 256) {
                    float cc = 0.f;
#pragma unroll
                    for (int k = 0; k < KK_; k++) cc = fmaf(sh_alpha[k], sp[(size_t)k * DD + d], cc);
                    float sv = cc + sh_h[d];
                    bf16 shh = __float2bfloat16(sv);
                    g_shi[(size_t)(b * TT + t) * DD + d] = shh;
                    g_slo[(size_t)(b * TT + t) * DD + d] = __float2bfloat16(sv - __bfloat162float(shh));
                }
            }
        }
        gridbar();
        cur ^= 1;
    }
}

// -------------------- launch --------------------
extern "C" void kernel_launch(void* const* d_in, const int* in_sizes, int n_in,
                              void* d_out, int out_size)
{
    const float* spatial      = (const float*)d_in[0];
    const float* global_feats = (const float*)d_in[1];
    const int*   captions     = (const int*)d_in[2];
    const int*   lengths      = (const int*)d_in[3];
    const float* emb          = (const float*)d_in[4];
    const float* W_init_h     = (const float*)d_in[5];
    const float* b_init_h     = (const float*)d_in[6];
    const float* W_init_m     = (const float*)d_in[7];
    const float* b_init_m     = (const float*)d_in[8];
    const float* W_ih         = (const float*)d_in[9];
    const float* b_ih         = (const float*)d_in[10];
    const float* W_hh         = (const float*)d_in[11];
    const float* b_hh         = (const float*)d_in[12];
    const float* Wv           = (const float*)d_in[13];
    const float* bv           = (const float*)d_in[14];
    const float* Wg           = (const float*)d_in[15];
    const float* bg           = (const float*)d_in[16];
    const float* wh           = (const float*)d_in[17];
    const float* bh_att       = (const float*)d_in[18];
    const float* Wp           = (const float*)d_in[19];
    const float* bp           = (const float*)d_in[20];
    float* out = (float*)d_out;

#define GETP(var, sym) void* var; cudaGetSymbolAddress(&var, sym)
    GETP(p_embhi, g_embhi);  GETP(p_emblo, g_emblo);
    GETP(p_glhi, g_glhi);    GETP(p_gllo, g_gllo);
    GETP(p_wihehi, g_wihehi);GETP(p_wihelo, g_wihelo);
    GETP(p_wcathi, g_wcathi);GETP(p_wcatlo, g_wcatlo);
    GETP(p_whhhi, g_whhhi);  GETP(p_whhlo, g_whhlo);
    GETP(p_wvhi, g_wvhi);    GETP(p_wvlo, g_wvlo);
    GETP(p_wphi, g_wphi);    GETP(p_wplo, g_wplo);
    GETP(p_sphi, g_sphi);    GETP(p_splo, g_splo);
    GETP(p_shi, g_shi);      GETP(p_slo, g_slo);
    GETP(p_gatesx, g_gatesx);
    GETP(p_ipart, g_ipart);  GETP(p_vpart, g_vpart);
#undef GETP

    const int GSM = 2 * 4 * SMATB * 2;                       // 81920 B
    const int RSM = 4 * RMATB * 2 + (DD + 3 * 52) * 4;
    cudaFuncSetAttribute(gemm_hl, cudaFuncAttributeMaxDynamicSharedMemorySize, GSM);
    cudaFuncSetAttribute(recur_kernel, cudaFuncAttributeMaxDynamicSharedMemorySize, RSM);

    // ---- 1. split all fp32 operands into bf16 hi/lo ----
    SegArr sa;
    long long pos = 0;
    auto seg = [&](int i, const float* src, void* hi, void* lo, int srcld, int cols, int rows) {
        sa.s[i].src = (const float4*)src;
        sa.s[i].hi = (uint2*)hi;  sa.s[i].lo = (uint2*)lo;
        sa.s[i].srcld4 = srcld / 4;
        sa.s[i].lc4 = (cols / 4 == 64) ? 6 : 7;
        sa.s[i].start = pos;
        pos += (long long)rows * (cols / 4);
    };
    seg(0, global_feats, p_glhi, p_gllo, DD, DD, BQ);
    seg(1, W_init_h, p_wcathi, p_wcatlo, DD, DD, DD);
    seg(2, W_init_m, (bf16*)p_wcathi + 512 * DD, (bf16*)p_wcatlo + 512 * DD, DD, DD, DD);
    seg(3, W_ih, p_wihehi, p_wihelo, EE + DD, EE, G4);
    seg(4, W_ih + EE, (bf16*)p_wcathi + 1024 * DD, (bf16*)p_wcatlo + 1024 * DD, EE + DD, DD, G4);
    seg(5, W_hh, p_whhhi, p_whhlo, DD, DD, G4);
    seg(6, Wv, p_wvhi, p_wvlo, DD, DD, KK_);
    seg(7, Wp, p_wphi, p_wplo, DD, DD, VV);
    seg(8, spatial, p_sphi, p_splo, DD, DD, BQ * KK_);
    sa.total = pos;
    split_all<<<(unsigned)((pos + 255) / 256), 256>>>(sa);

    // ---- 2. gather caption embeddings (bf16 hi/lo) ----
    gather_emb<<<(BQ * TT * (EE / 4) + 255) / 256, 256>>>(captions, emb);

    // ---- 3. vproj partials: spatial @ Wv^T, split-K x2 ----
    gemm_hl<<<dim3(1, 49, 2), 256, GSM>>>((bf16*)p_sphi, (bf16*)p_splo, DD,
        (bf16*)p_wvhi, (bf16*)p_wvlo, DD, nullptr, KK_, BQ * KK_, KK_, 256,
        nullptr, nullptr, 1, (float*)p_vpart, (long)BQ * KK_ * KK_);

    // ---- 4. gates_x = embseq @ W_ih[:,:E]^T (no bias; gxg added at consume) ----
    gemm_hl<<<dim3(16, 20), 256, GSM>>>((bf16*)p_embhi, (bf16*)p_emblo, EE,
        (bf16*)p_wihehi, (bf16*)p_wihelo, EE, (float*)p_gatesx, G4, BQ * TT, G4, EE,
        nullptr, nullptr, 1, nullptr, 0);

    // ---- 5. init partials: global @ [Winit_h;Winit_m;W_ihD]^T, split-K x4 ----
    gemm_hl<<<dim3(24, 1, 4), 256, GSM>>>((bf16*)p_glhi, (bf16*)p_gllo, DD,
        (bf16*)p_wcathi, (bf16*)p_wcatlo, DD, nullptr, 3072, BQ, 3072, 128,
        nullptr, nullptr, 1, (float*)p_ipart, (long)BQ * 3072);

    // ---- 6. recurrence (inline-reduces init & vproj partials in prologue) ----
    recur_kernel<<<128, 256, RSM>>>(b_hh, lengths, spatial, Wg, bg, wh, bh_att,
                                    b_init_h, b_init_m, b_ih, bv);

    // ---- 7. logits = s @ Wp^T + bp (masked) ----
    gemm_hl<<<dim3(79, 20), 256, GSM>>>((bf16*)p_shi, (bf16*)p_slo, DD,
        (bf16*)p_wphi, (bf16*)p_wplo, DD, out, VV, BQ * TT, VV, DD,
        bp, lengths, TT, nullptr, 0);
}